// round 1
// baseline (speedup 1.0000x reference)
#include <cuda_runtime.h>
#include <cuda_bf16.h>
#include <math.h>

// Problem constants
#define GN   32768
#define GLD  256
#define GD   512
#define KS   1024
#define KM   4096

// ---------------- scratch (static __device__, no allocation) ----------------
static __device__ float g_esum_syn[KS * GD];     // 2 MB
static __device__ float g_esum_sem[KM * GD];     // 8 MB
static __device__ float g_counts_syn[KS];
static __device__ float g_counts_sem[KM];
static __device__ int   g_pair_syn[(size_t)KS * KS];   // 4 MB
static __device__ int   g_pair_sem[(size_t)KM * KM];   // 64 MB
static __device__ int   g_idx_syn[GN];
static __device__ int   g_idx_sem[GN];
static __device__ float g_cnorm_syn[KS];
static __device__ float g_cnorm_sem[KM];
static __device__ float g_clnew_syn[KS];
static __device__ float g_clnew_sem[KM];
static __device__ float g_nsum[2];
static __device__ float g_loss[1];

// ---------------- helpers ----------------
__device__ __forceinline__ float blk_reduce_256(float v) {
    __shared__ float sh[8];
    int lane = threadIdx.x & 31, w = threadIdx.x >> 5;
#pragma unroll
    for (int o = 16; o; o >>= 1) v += __shfl_down_sync(0xffffffffu, v, o);
    if (lane == 0) sh[w] = v;
    __syncthreads();
    if (w == 0) {
        v = (lane < 8) ? sh[lane] : 0.f;
#pragma unroll
        for (int o = 4; o; o >>= 1) v += __shfl_down_sync(0xffffffffu, v, o);
    }
    return v;  // valid on thread 0
}

// ---------------- code row norms ----------------
__global__ void rownorm_kernel(const float* __restrict__ cb, float* __restrict__ out) {
    int k = blockIdx.x;
    const float* row = cb + (size_t)k * GD;
    float s = 0.f;
    for (int d = threadIdx.x; d < GD; d += 256) {
        float v = row[d];
        s = fmaf(v, v, s);
    }
    s = blk_reduce_256(s);
    if (threadIdx.x == 0) out[k] = s;
}

// ---------------- fused GEMM + argmin (fp32, f32x2-packed) ----------------
// dist(n,k) = ||c_k||^2 - 2 * z_n . c_k   (argmin-equivalent to full distance)
// BM=64 rows, BN=64 codes, 256 threads, 4x4 microtile, 2 D-lanes per fma.rn.f32x2.
__global__ __launch_bounds__(256) void argmin_kernel(
    const float* __restrict__ zre, const float* __restrict__ zim,
    const float* __restrict__ cb, const float* __restrict__ cnorm,
    int K, int* __restrict__ idx_out)
{
    __shared__ __align__(16) float sz[64 * 34];
    __shared__ __align__(16) float sc[64 * 34];
    __shared__ float rv[64 * 16];
    __shared__ int   rk[64 * 16];

    const int t = threadIdx.x;
    const int tx = t & 15, ty = t >> 4;
    const int rowBase = blockIdx.x * 64;

    float bestv[4];
    int   bestk[4];
#pragma unroll
    for (int i = 0; i < 4; i++) { bestv[i] = 3.4e38f; bestk[i] = 0; }

    const unsigned long long* szq = reinterpret_cast<const unsigned long long*>(sz);
    const unsigned long long* scq = reinterpret_cast<const unsigned long long*>(sc);

    for (int kb = 0; kb < K; kb += 64) {
        unsigned long long acc[4][4];
#pragma unroll
        for (int i = 0; i < 4; i++)
#pragma unroll
            for (int j = 0; j < 4; j++) acc[i][j] = 0ull;

        for (int dbase = 0; dbase < GD; dbase += 32) {
            __syncthreads();
            // 64 rows x 32 floats = 512 float4 per array; 2 float4 per thread each
#pragma unroll
            for (int u = 0; u < 2; u++) {
                int id = t + 256 * u;
                int r = id >> 3, c4 = id & 7;
                int dg = dbase + c4 * 4;
                const float* zsrc = (dg < GLD)
                    ? (zre + (size_t)(rowBase + r) * GLD + dg)
                    : (zim + (size_t)(rowBase + r) * GLD + (dg - GLD));
                float4 v = *reinterpret_cast<const float4*>(zsrc);
                float* dz = &sz[r * 34 + c4 * 4];
                dz[0] = v.x; dz[1] = v.y; dz[2] = v.z; dz[3] = v.w;
                float4 w = *reinterpret_cast<const float4*>(
                    cb + (size_t)(kb + r) * GD + dbase + c4 * 4);
                float* dc = &sc[r * 34 + c4 * 4];
                dc[0] = w.x; dc[1] = w.y; dc[2] = w.z; dc[3] = w.w;
            }
            __syncthreads();
#pragma unroll
            for (int dp = 0; dp < 16; dp++) {
                unsigned long long za[4], ca[4];
#pragma unroll
                for (int i = 0; i < 4; i++) za[i] = szq[(ty + 16 * i) * 17 + dp];
#pragma unroll
                for (int j = 0; j < 4; j++) ca[j] = scq[(tx + 16 * j) * 17 + dp];
#pragma unroll
                for (int i = 0; i < 4; i++)
#pragma unroll
                    for (int j = 0; j < 4; j++)
                        asm("fma.rn.f32x2 %0, %1, %2, %0;"
                            : "+l"(acc[i][j]) : "l"(za[i]), "l"(ca[j]));
            }
        }
        // epilogue: fold this K-tile into the running argmin
#pragma unroll
        for (int j = 0; j < 4; j++) {
            int k = kb + tx + 16 * j;
            float cn = __ldg(&cnorm[k]);
#pragma unroll
            for (int i = 0; i < 4; i++) {
                float2 a = *reinterpret_cast<float2*>(&acc[i][j]);
                float dist = fmaf(-2.f, a.x + a.y, cn);
                if (dist < bestv[i]) { bestv[i] = dist; bestk[i] = k; }
            }
        }
    }

#pragma unroll
    for (int i = 0; i < 4; i++) {
        rv[(ty + 16 * i) * 16 + tx] = bestv[i];
        rk[(ty + 16 * i) * 16 + tx] = bestk[i];
    }
    __syncthreads();
    if (t < 64) {
        float bv = 3.4e38f; int bk = 0x7fffffff;
        for (int x = 0; x < 16; x++) {
            float v = rv[t * 16 + x]; int k = rk[t * 16 + x];
            if (v < bv || (v == bv && k < bk)) { bv = v; bk = k; }
        }
        idx_out[rowBase + t] = bk;
    }
}

// ---------------- scatter: counts, pair counts, embed_sum ----------------
__global__ void scatter_kernel(
    const float* __restrict__ zre, const float* __restrict__ zim,
    const int* __restrict__ idx, const int* __restrict__ prev,
    float* __restrict__ counts, float* __restrict__ esum,
    int* __restrict__ pair, int K)
{
    int n = blockIdx.x;
    int i = idx[n];
    int t = threadIdx.x;
    if (t == 0) {
        atomicAdd(&counts[i], 1.f);
        atomicAdd(&pair[(size_t)prev[n] * K + i], 1);
    }
    const float* zr = zre + (size_t)n * GLD;
    const float* zi = zim + (size_t)n * GLD;
    float* es = esum + (size_t)i * GD;
    for (int d = t; d < GLD; d += 256) {
        atomicAdd(&es[d], zr[d]);
        atomicAdd(&es[d + GLD], zi[d]);
    }
}

// ---------------- cluster_size EMA + n reduction ----------------
__global__ void clnew_kernel(const float* __restrict__ cl, const float* __restrict__ counts,
                             float* __restrict__ clnew, float* __restrict__ nsum, int K)
{
    int k = blockIdx.x * 256 + threadIdx.x;
    float v = 0.f;
    if (k < K) {
        v = cl[k] * 0.99f + 0.01f * counts[k];
        clnew[k] = v;
    }
    v = blk_reduce_256(v);
    if (threadIdx.x == 0) atomicAdd(nsum, v);
}

// ---------------- codebook EMA update ----------------
__global__ void cbnew_kernel(const float* __restrict__ avg, const float* __restrict__ esum,
                             const float* __restrict__ clnew, const float* __restrict__ nsum,
                             float* __restrict__ out, int K)
{
    size_t idx = (size_t)blockIdx.x * 256 + threadIdx.x;
    int k = (int)(idx >> 9);
    float n = *nsum;
    float cs = (clnew[k] + 1e-6f) / (n + (float)K * 1e-6f) * n;
    float a = avg[idx] * 0.99f + 0.01f * esum[idx];
    out[idx] = a / cs;
}

// ---------------- zq gather + loss accumulation + idx-as-float ----------------
__global__ void gather_loss_kernel(
    const float* __restrict__ zre, const float* __restrict__ zim,
    const int* __restrict__ idx, const float* __restrict__ cb,
    float* __restrict__ zq, float* __restrict__ idxf, float* __restrict__ lacc)
{
    int n = blockIdx.x;
    int i = idx[n];
    int t = threadIdx.x;
    if (t == 0) idxf[n] = (float)i;
    const float* crow = cb + (size_t)i * GD;
    float s = 0.f;
    for (int d = t; d < GD; d += 256) {
        float q = crow[d];
        float z = (d < GLD) ? zre[(size_t)n * GLD + d]
                            : zim[(size_t)n * GLD + d - GLD];
        zq[(size_t)n * GD + d] = q;
        float df = q - z;
        s = fmaf(df, df, s);
    }
    s = blk_reduce_256(s);
    if (t == 0) atomicAdd(lacc, s);
}

__global__ void finalize_loss_kernel(const float* __restrict__ lacc, float* __restrict__ out) {
    // loss = sum over both codebooks of 1.25 * mean((zq - z)^2), mean over N*D
    out[0] = 1.25f * lacc[0] / 16777216.f;
}

// ---------------- adjacency transform ----------------
__global__ void adj_kernel(const float* __restrict__ adj, const int* __restrict__ cnt,
                           float* __restrict__ out, size_t total)
{
    size_t i = (size_t)blockIdx.x * 256 + threadIdx.x;
    if (i >= total) return;
    int c = cnt[i];
    float a = adj[i];
    if (c == 0) { out[i] = a; return; }
    float p = powf(0.99f, (float)c);
    out[i] = a * p + (1.f - p) / 0.01f;
}

// ---------------- launch ----------------
extern "C" void kernel_launch(void* const* d_in, const int* in_sizes, int n_in,
                              void* d_out, int out_size)
{
    const float* zre_f = (const float*)d_in[0];   // z_fast_real [N,256]
    const float* zim_f = (const float*)d_in[1];   // z_fast_imag
    const float* zre_s = (const float*)d_in[2];   // z_slow_real
    const float* zim_s = (const float*)d_in[3];   // z_slow_imag
    const int*   prev_syn = (const int*)d_in[4];
    const int*   prev_sem = (const int*)d_in[5];
    const float* cb_syn = (const float*)d_in[6];  // [KS,512]
    const float* cb_sem = (const float*)d_in[7];  // [KM,512]
    const float* cl_syn = (const float*)d_in[8];
    const float* avg_syn = (const float*)d_in[9];
    const float* cl_sem = (const float*)d_in[10];
    const float* avg_sem = (const float*)d_in[11];
    const float* adj_syn = (const float*)d_in[12];
    const float* adj_sem = (const float*)d_in[13];

    float* out = (float*)d_out;
    const size_t OFF_ZQ_SYN = 0;
    const size_t OFF_ZQ_SEM = OFF_ZQ_SYN + (size_t)GN * GD;
    const size_t OFF_LOSS   = OFF_ZQ_SEM + (size_t)GN * GD;
    const size_t OFF_IDX_SYN = OFF_LOSS + 1;
    const size_t OFF_IDX_SEM = OFF_IDX_SYN + GN;
    const size_t OFF_CB_SYN  = OFF_IDX_SEM + GN;
    const size_t OFF_CB_SEM  = OFF_CB_SYN + (size_t)KS * GD;
    const size_t OFF_ADJ_SYN = OFF_CB_SEM + (size_t)KM * GD;
    const size_t OFF_ADJ_SEM = OFF_ADJ_SYN + (size_t)KS * KS;

    // resolve scratch symbol addresses (pure queries; capture-safe)
    void *p_esum_syn, *p_esum_sem, *p_cnt_syn, *p_cnt_sem, *p_pair_syn, *p_pair_sem;
    void *p_idx_syn, *p_idx_sem, *p_cn_syn, *p_cn_sem, *p_cl_syn, *p_cl_sem, *p_nsum, *p_loss;
    cudaGetSymbolAddress(&p_esum_syn, g_esum_syn);
    cudaGetSymbolAddress(&p_esum_sem, g_esum_sem);
    cudaGetSymbolAddress(&p_cnt_syn, g_counts_syn);
    cudaGetSymbolAddress(&p_cnt_sem, g_counts_sem);
    cudaGetSymbolAddress(&p_pair_syn, g_pair_syn);
    cudaGetSymbolAddress(&p_pair_sem, g_pair_sem);
    cudaGetSymbolAddress(&p_idx_syn, g_idx_syn);
    cudaGetSymbolAddress(&p_idx_sem, g_idx_sem);
    cudaGetSymbolAddress(&p_cn_syn, g_cnorm_syn);
    cudaGetSymbolAddress(&p_cn_sem, g_cnorm_sem);
    cudaGetSymbolAddress(&p_cl_syn, g_clnew_syn);
    cudaGetSymbolAddress(&p_cl_sem, g_clnew_sem);
    cudaGetSymbolAddress(&p_nsum, g_nsum);
    cudaGetSymbolAddress(&p_loss, g_loss);

    // 1) zero scratch
    cudaMemsetAsync(p_esum_syn, 0, (size_t)KS * GD * sizeof(float));
    cudaMemsetAsync(p_esum_sem, 0, (size_t)KM * GD * sizeof(float));
    cudaMemsetAsync(p_cnt_syn, 0, KS * sizeof(float));
    cudaMemsetAsync(p_cnt_sem, 0, KM * sizeof(float));
    cudaMemsetAsync(p_pair_syn, 0, (size_t)KS * KS * sizeof(int));
    cudaMemsetAsync(p_pair_sem, 0, (size_t)KM * KM * sizeof(int));
    cudaMemsetAsync(p_nsum, 0, 2 * sizeof(float));
    cudaMemsetAsync(p_loss, 0, sizeof(float));

    // 2) code norms
    rownorm_kernel<<<KS, 256>>>(cb_syn, (float*)p_cn_syn);
    rownorm_kernel<<<KM, 256>>>(cb_sem, (float*)p_cn_sem);

    // 3) fused GEMM + argmin
    argmin_kernel<<<GN / 64, 256>>>(zre_f, zim_f, cb_syn, (const float*)p_cn_syn,
                                    KS, (int*)p_idx_syn);
    argmin_kernel<<<GN / 64, 256>>>(zre_s, zim_s, cb_sem, (const float*)p_cn_sem,
                                    KM, (int*)p_idx_sem);

    // 4) scatter reductions
    scatter_kernel<<<GN, 256>>>(zre_f, zim_f, (const int*)p_idx_syn, prev_syn,
                                (float*)p_cnt_syn, (float*)p_esum_syn,
                                (int*)p_pair_syn, KS);
    scatter_kernel<<<GN, 256>>>(zre_s, zim_s, (const int*)p_idx_sem, prev_sem,
                                (float*)p_cnt_sem, (float*)p_esum_sem,
                                (int*)p_pair_sem, KM);

    // 5) cluster size EMA + n
    clnew_kernel<<<KS / 256, 256>>>(cl_syn, (const float*)p_cnt_syn,
                                    (float*)p_cl_syn, (float*)p_nsum, KS);
    clnew_kernel<<<KM / 256, 256>>>(cl_sem, (const float*)p_cnt_sem,
                                    (float*)p_cl_sem, ((float*)p_nsum) + 1, KM);

    // 6) codebook EMA update (writes directly to output)
    cbnew_kernel<<<(KS * GD) / 256, 256>>>(avg_syn, (const float*)p_esum_syn,
                                           (const float*)p_cl_syn, (const float*)p_nsum,
                                           out + OFF_CB_SYN, KS);
    cbnew_kernel<<<(KM * GD) / 256, 256>>>(avg_sem, (const float*)p_esum_sem,
                                           (const float*)p_cl_sem, ((const float*)p_nsum) + 1,
                                           out + OFF_CB_SEM, KM);

    // 7) zq gather + loss + idx output
    gather_loss_kernel<<<GN, 256>>>(zre_f, zim_f, (const int*)p_idx_syn, cb_syn,
                                    out + OFF_ZQ_SYN, out + OFF_IDX_SYN, (float*)p_loss);
    gather_loss_kernel<<<GN, 256>>>(zre_s, zim_s, (const int*)p_idx_sem, cb_sem,
                                    out + OFF_ZQ_SEM, out + OFF_IDX_SEM, (float*)p_loss);

    // 8) loss finalize
    finalize_loss_kernel<<<1, 1>>>((const float*)p_loss, out + OFF_LOSS);

    // 9) adjacency transform
    {
        size_t tot = (size_t)KS * KS;
        adj_kernel<<<(unsigned)((tot + 255) / 256), 256>>>(adj_syn, (const int*)p_pair_syn,
                                                           out + OFF_ADJ_SYN, tot);
    }
    {
        size_t tot = (size_t)KM * KM;
        adj_kernel<<<(unsigned)((tot + 255) / 256), 256>>>(adj_sem, (const int*)p_pair_sem,
                                                           out + OFF_ADJ_SEM, tot);
    }
    (void)in_sizes; (void)n_in; (void)out_size;
}

// round 2
// speedup vs baseline: 1.1851x; 1.1851x over previous
#include <cuda_runtime.h>
#include <cuda_bf16.h>
#include <math.h>

// Problem constants
#define GN   32768
#define GLD  256
#define GD   512
#define KS   1024
#define KM   4096
#define NUNITS 1280   // 256 syn units + 1024 sem units (256 row-tiles x 4 k-chunks)

// ---------------- scratch (static __device__, no allocation) ----------------
static __device__ float g_esum_syn[KS * GD];
static __device__ float g_esum_sem[KM * GD];
static __device__ float g_counts_syn[KS];
static __device__ float g_counts_sem[KM];
static __device__ int   g_pair_syn[(size_t)KS * KS];
static __device__ int   g_pair_sem[(size_t)KM * KM];
static __device__ int   g_idx_syn[GN];
static __device__ int   g_idx_sem[GN];
static __device__ float g_cnorm_syn[KS];
static __device__ float g_cnorm_sem[KM];
static __device__ float g_clnew_syn[KS];
static __device__ float g_clnew_sem[KM];
static __device__ float g_nsum[2];
static __device__ float g_loss[1];
static __device__ float g_pbv[(size_t)NUNITS * 128];
static __device__ int   g_pbk[(size_t)NUNITS * 128];

// ---------------- helpers ----------------
__device__ __forceinline__ float blk_reduce_256(float v) {
    __shared__ float sh[8];
    int lane = threadIdx.x & 31, w = threadIdx.x >> 5;
#pragma unroll
    for (int o = 16; o; o >>= 1) v += __shfl_down_sync(0xffffffffu, v, o);
    if (lane == 0) sh[w] = v;
    __syncthreads();
    if (w == 0) {
        v = (lane < 8) ? sh[lane] : 0.f;
#pragma unroll
        for (int o = 4; o; o >>= 1) v += __shfl_down_sync(0xffffffffu, v, o);
    }
    return v;  // valid on thread 0
}

// ---------------- code row norms ----------------
__global__ void rownorm_kernel(const float* __restrict__ cb, float* __restrict__ out) {
    int k = blockIdx.x;
    const float* row = cb + (size_t)k * GD;
    float s = 0.f;
    for (int d = threadIdx.x; d < GD; d += 256) {
        float v = row[d];
        s = fmaf(v, v, s);
    }
    s = blk_reduce_256(s);
    if (threadIdx.x == 0) out[k] = s;
}

// ---------------- fused GEMM + argmin, 8x8 microtile, f32x2 ----------------
// Each work unit: 128 rows x 1024 codes x D=512.
// dist(n,k) = ||c_k||^2 - 2 z_n.c_k (row-constant ||z||^2 dropped).
__global__ __launch_bounds__(256, 1) void dist_kernel(
    const float* __restrict__ zreA, const float* __restrict__ zimA,
    const float* __restrict__ cbA, const float* __restrict__ cnA,
    const float* __restrict__ zreB, const float* __restrict__ zimB,
    const float* __restrict__ cbB, const float* __restrict__ cnB,
    float* __restrict__ bvout, int* __restrict__ bkout)
{
    __shared__ __align__(16) float sz[128 * 20];
    __shared__ __align__(16) float sc[128 * 20];
    __shared__ float rv[128 * 16];
    __shared__ int   rk[128 * 16];

    const int u = blockIdx.x;
    const float *zre, *zim, *cb, *cn;
    int rowBase, kBase;
    if (u < 256) {
        zre = zreA; zim = zimA; cb = cbA; cn = cnA;
        rowBase = u * 128; kBase = 0;
    } else {
        int v = u - 256;
        zre = zreB; zim = zimB; cb = cbB; cn = cnB;
        rowBase = (v >> 2) * 128; kBase = (v & 3) * 1024;
    }

    const int t = threadIdx.x;
    const int lane = t & 31, w = t >> 5;
    const int wr = w >> 2, wc = w & 3;      // warp row 0..1, warp col 0..3
    const int lr = lane >> 2, lc = lane & 3; // lane row 0..7, lane col 0..3

    const int gr0 = t >> 2;          // staging row 0..63 (and +64)
    const int gc4 = (t & 3) * 4;     // staging float offset 0/4/8/12

    float bestv[8]; int bestk[8];
#pragma unroll
    for (int i = 0; i < 8; i++) { bestv[i] = 3.4e38f; bestk[i] = 0; }

    const float* szp = sz + (wr * 64 + lr) * 20;
    const float* scp = sc + (wc * 32 + lc) * 20;

    for (int kb = 0; kb < 1024; kb += 128) {
        unsigned long long acc[8][8];
#pragma unroll
        for (int i = 0; i < 8; i++)
#pragma unroll
            for (int j = 0; j < 8; j++) acc[i][j] = 0ull;

        float4 vz0, vz1, vc0, vc1;
        {   // prefetch stage db=0 (dg<256 always)
            vz0 = *(const float4*)(zre + (size_t)(rowBase + gr0) * GLD + gc4);
            vz1 = *(const float4*)(zre + (size_t)(rowBase + gr0 + 64) * GLD + gc4);
            vc0 = *(const float4*)(cb + (size_t)(kBase + kb + gr0) * GD + gc4);
            vc1 = *(const float4*)(cb + (size_t)(kBase + kb + gr0 + 64) * GD + gc4);
        }
        for (int db = 0; db < GD; db += 16) {
            __syncthreads();
            *(float4*)&sz[gr0 * 20 + gc4]        = vz0;
            *(float4*)&sz[(gr0 + 64) * 20 + gc4] = vz1;
            *(float4*)&sc[gr0 * 20 + gc4]        = vc0;
            *(float4*)&sc[(gr0 + 64) * 20 + gc4] = vc1;
            __syncthreads();
            int dn = db + 16;
            if (dn < GD) {
                int dg = dn + gc4;
                const float* z0 = (dg < GLD)
                    ? zre + (size_t)(rowBase + gr0) * GLD + dg
                    : zim + (size_t)(rowBase + gr0) * GLD + (dg - GLD);
                const float* z1 = (dg < GLD)
                    ? zre + (size_t)(rowBase + gr0 + 64) * GLD + dg
                    : zim + (size_t)(rowBase + gr0 + 64) * GLD + (dg - GLD);
                vz0 = *(const float4*)z0;
                vz1 = *(const float4*)z1;
                vc0 = *(const float4*)(cb + (size_t)(kBase + kb + gr0) * GD + dg);
                vc1 = *(const float4*)(cb + (size_t)(kBase + kb + gr0 + 64) * GD + dg);
            }
#pragma unroll
            for (int p4 = 0; p4 < 4; p4++) {
                ulonglong2 za[8], ca[8];
#pragma unroll
                for (int i = 0; i < 8; i++)
                    za[i] = *(const ulonglong2*)(szp + i * 160 + p4 * 4);
#pragma unroll
                for (int j = 0; j < 8; j++)
                    ca[j] = *(const ulonglong2*)(scp + j * 80 + p4 * 4);
#pragma unroll
                for (int i = 0; i < 8; i++)
#pragma unroll
                    for (int j = 0; j < 8; j++) {
                        asm("fma.rn.f32x2 %0, %1, %2, %0;"
                            : "+l"(acc[i][j]) : "l"(za[i].x), "l"(ca[j].x));
                        asm("fma.rn.f32x2 %0, %1, %2, %0;"
                            : "+l"(acc[i][j]) : "l"(za[i].y), "l"(ca[j].y));
                    }
            }
        }
        // fold this 128-code tile into the running argmin
#pragma unroll
        for (int j = 0; j < 8; j++) {
            int k = kBase + kb + wc * 32 + lc + j * 4;
            float cnv = __ldg(&cn[k]);
#pragma unroll
            for (int i = 0; i < 8; i++) {
                float2 a = *reinterpret_cast<float2*>(&acc[i][j]);
                float dist = fmaf(-2.f, a.x + a.y, cnv);
                if (dist < bestv[i]) { bestv[i] = dist; bestk[i] = k; }
            }
        }
    }

    // cross-thread reduction: 16 candidates per row
#pragma unroll
    for (int i = 0; i < 8; i++) {
        int r = wr * 64 + lr + i * 8;
        rv[r * 16 + wc * 4 + lc] = bestv[i];
        rk[r * 16 + wc * 4 + lc] = bestk[i];
    }
    __syncthreads();
    if (t < 128) {
        float bv = 3.4e38f; int bk = 0x7fffffff;
#pragma unroll
        for (int x = 0; x < 16; x++) {
            float v = rv[t * 16 + x]; int k = rk[t * 16 + x];
            if (v < bv || (v == bv && k < bk)) { bv = v; bk = k; }
        }
        bvout[(size_t)u * 128 + t] = bv;
        bkout[(size_t)u * 128 + t] = bk;
    }
}

// ---------------- combine partial argmins ----------------
__global__ void combine_kernel(const float* __restrict__ bv, const int* __restrict__ bk,
                               int* __restrict__ idx_syn, int* __restrict__ idx_sem)
{
    int n = blockIdx.x * 256 + threadIdx.x;  // 0..GN-1
    int tile = n >> 7, r = n & 127;
    idx_syn[n] = bk[(size_t)tile * 128 + r];
    float bvv = 3.4e38f; int bki = 0x7fffffff;
#pragma unroll
    for (int c = 0; c < 4; c++) {
        size_t uu = (size_t)(256 + tile * 4 + c) * 128 + r;
        float v = bv[uu]; int k = bk[uu];
        if (v < bvv || (v == bvv && k < bki)) { bvv = v; bki = k; }
    }
    idx_sem[n] = bki;
}

// ---------------- scatter: counts, pair counts, embed_sum ----------------
__global__ void scatter_kernel(
    const float* __restrict__ zre, const float* __restrict__ zim,
    const int* __restrict__ idx, const int* __restrict__ prev,
    float* __restrict__ counts, float* __restrict__ esum,
    int* __restrict__ pair, int K)
{
    int n = blockIdx.x;
    int i = idx[n];
    int t = threadIdx.x;
    if (t == 0) {
        atomicAdd(&counts[i], 1.f);
        atomicAdd(&pair[(size_t)prev[n] * K + i], 1);
    }
    const float* zr = zre + (size_t)n * GLD;
    const float* zi = zim + (size_t)n * GLD;
    float* es = esum + (size_t)i * GD;
    for (int d = t; d < GLD; d += 256) {
        atomicAdd(&es[d], zr[d]);
        atomicAdd(&es[d + GLD], zi[d]);
    }
}

// ---------------- cluster_size EMA + n reduction ----------------
__global__ void clnew_kernel(const float* __restrict__ cl, const float* __restrict__ counts,
                             float* __restrict__ clnew, float* __restrict__ nsum, int K)
{
    int k = blockIdx.x * 256 + threadIdx.x;
    float v = 0.f;
    if (k < K) {
        v = cl[k] * 0.99f + 0.01f * counts[k];
        clnew[k] = v;
    }
    v = blk_reduce_256(v);
    if (threadIdx.x == 0) atomicAdd(nsum, v);
}

// ---------------- codebook EMA update ----------------
__global__ void cbnew_kernel(const float* __restrict__ avg, const float* __restrict__ esum,
                             const float* __restrict__ clnew, const float* __restrict__ nsum,
                             float* __restrict__ out, int K)
{
    size_t idx = (size_t)blockIdx.x * 256 + threadIdx.x;
    int k = (int)(idx >> 9);
    float n = *nsum;
    float cs = (clnew[k] + 1e-6f) / (n + (float)K * 1e-6f) * n;
    float a = avg[idx] * 0.99f + 0.01f * esum[idx];
    out[idx] = a / cs;
}

// ---------------- zq gather + loss accumulation + idx-as-float ----------------
__global__ void gather_loss_kernel(
    const float* __restrict__ zre, const float* __restrict__ zim,
    const int* __restrict__ idx, const float* __restrict__ cb,
    float* __restrict__ zq, float* __restrict__ idxf, float* __restrict__ lacc)
{
    int n = blockIdx.x;
    int i = idx[n];
    int t = threadIdx.x;
    if (t == 0) idxf[n] = (float)i;
    const float* crow = cb + (size_t)i * GD;
    float s = 0.f;
    for (int d = t; d < GD; d += 256) {
        float q = crow[d];
        float z = (d < GLD) ? zre[(size_t)n * GLD + d]
                            : zim[(size_t)n * GLD + d - GLD];
        zq[(size_t)n * GD + d] = q;
        float df = q - z;
        s = fmaf(df, df, s);
    }
    s = blk_reduce_256(s);
    if (t == 0) atomicAdd(lacc, s);
}

__global__ void finalize_loss_kernel(const float* __restrict__ lacc, float* __restrict__ out) {
    out[0] = 1.25f * lacc[0] / 16777216.f;
}

// ---------------- adjacency transform ----------------
__global__ void adj_kernel(const float* __restrict__ adj, const int* __restrict__ cnt,
                           float* __restrict__ out, size_t total)
{
    size_t i = (size_t)blockIdx.x * 256 + threadIdx.x;
    if (i >= total) return;
    int c = cnt[i];
    float a = adj[i];
    if (c == 0) { out[i] = a; return; }
    float p = powf(0.99f, (float)c);
    out[i] = a * p + (1.f - p) / 0.01f;
}

// ---------------- launch ----------------
extern "C" void kernel_launch(void* const* d_in, const int* in_sizes, int n_in,
                              void* d_out, int out_size)
{
    const float* zre_f = (const float*)d_in[0];
    const float* zim_f = (const float*)d_in[1];
    const float* zre_s = (const float*)d_in[2];
    const float* zim_s = (const float*)d_in[3];
    const int*   prev_syn = (const int*)d_in[4];
    const int*   prev_sem = (const int*)d_in[5];
    const float* cb_syn = (const float*)d_in[6];
    const float* cb_sem = (const float*)d_in[7];
    const float* cl_syn = (const float*)d_in[8];
    const float* avg_syn = (const float*)d_in[9];
    const float* cl_sem = (const float*)d_in[10];
    const float* avg_sem = (const float*)d_in[11];
    const float* adj_syn = (const float*)d_in[12];
    const float* adj_sem = (const float*)d_in[13];

    float* out = (float*)d_out;
    const size_t OFF_ZQ_SYN = 0;
    const size_t OFF_ZQ_SEM = OFF_ZQ_SYN + (size_t)GN * GD;
    const size_t OFF_LOSS   = OFF_ZQ_SEM + (size_t)GN * GD;
    const size_t OFF_IDX_SYN = OFF_LOSS + 1;
    const size_t OFF_IDX_SEM = OFF_IDX_SYN + GN;
    const size_t OFF_CB_SYN  = OFF_IDX_SEM + GN;
    const size_t OFF_CB_SEM  = OFF_CB_SYN + (size_t)KS * GD;
    const size_t OFF_ADJ_SYN = OFF_CB_SEM + (size_t)KM * GD;
    const size_t OFF_ADJ_SEM = OFF_ADJ_SYN + (size_t)KS * KS;

    void *p_esum_syn, *p_esum_sem, *p_cnt_syn, *p_cnt_sem, *p_pair_syn, *p_pair_sem;
    void *p_idx_syn, *p_idx_sem, *p_cn_syn, *p_cn_sem, *p_cl_syn, *p_cl_sem, *p_nsum, *p_loss;
    void *p_pbv, *p_pbk;
    cudaGetSymbolAddress(&p_esum_syn, g_esum_syn);
    cudaGetSymbolAddress(&p_esum_sem, g_esum_sem);
    cudaGetSymbolAddress(&p_cnt_syn, g_counts_syn);
    cudaGetSymbolAddress(&p_cnt_sem, g_counts_sem);
    cudaGetSymbolAddress(&p_pair_syn, g_pair_syn);
    cudaGetSymbolAddress(&p_pair_sem, g_pair_sem);
    cudaGetSymbolAddress(&p_idx_syn, g_idx_syn);
    cudaGetSymbolAddress(&p_idx_sem, g_idx_sem);
    cudaGetSymbolAddress(&p_cn_syn, g_cnorm_syn);
    cudaGetSymbolAddress(&p_cn_sem, g_cnorm_sem);
    cudaGetSymbolAddress(&p_cl_syn, g_clnew_syn);
    cudaGetSymbolAddress(&p_cl_sem, g_clnew_sem);
    cudaGetSymbolAddress(&p_nsum, g_nsum);
    cudaGetSymbolAddress(&p_loss, g_loss);
    cudaGetSymbolAddress(&p_pbv, g_pbv);
    cudaGetSymbolAddress(&p_pbk, g_pbk);

    // 1) zero scratch
    cudaMemsetAsync(p_esum_syn, 0, (size_t)KS * GD * sizeof(float));
    cudaMemsetAsync(p_esum_sem, 0, (size_t)KM * GD * sizeof(float));
    cudaMemsetAsync(p_cnt_syn, 0, KS * sizeof(float));
    cudaMemsetAsync(p_cnt_sem, 0, KM * sizeof(float));
    cudaMemsetAsync(p_pair_syn, 0, (size_t)KS * KS * sizeof(int));
    cudaMemsetAsync(p_pair_sem, 0, (size_t)KM * KM * sizeof(int));
    cudaMemsetAsync(p_nsum, 0, 2 * sizeof(float));
    cudaMemsetAsync(p_loss, 0, sizeof(float));

    // 2) code norms
    rownorm_kernel<<<KS, 256>>>(cb_syn, (float*)p_cn_syn);
    rownorm_kernel<<<KM, 256>>>(cb_sem, (float*)p_cn_sem);

    // 3) fused GEMM + argmin over 1280 equal work units
    dist_kernel<<<NUNITS, 256>>>(zre_f, zim_f, cb_syn, (const float*)p_cn_syn,
                                 zre_s, zim_s, cb_sem, (const float*)p_cn_sem,
                                 (float*)p_pbv, (int*)p_pbk);
    combine_kernel<<<GN / 256, 256>>>((const float*)p_pbv, (const int*)p_pbk,
                                      (int*)p_idx_syn, (int*)p_idx_sem);

    // 4) scatter reductions
    scatter_kernel<<<GN, 256>>>(zre_f, zim_f, (const int*)p_idx_syn, prev_syn,
                                (float*)p_cnt_syn, (float*)p_esum_syn,
                                (int*)p_pair_syn, KS);
    scatter_kernel<<<GN, 256>>>(zre_s, zim_s, (const int*)p_idx_sem, prev_sem,
                                (float*)p_cnt_sem, (float*)p_esum_sem,
                                (int*)p_pair_sem, KM);

    // 5) cluster size EMA + n
    clnew_kernel<<<KS / 256, 256>>>(cl_syn, (const float*)p_cnt_syn,
                                    (float*)p_cl_syn, (float*)p_nsum, KS);
    clnew_kernel<<<KM / 256, 256>>>(cl_sem, (const float*)p_cnt_sem,
                                    (float*)p_cl_sem, ((float*)p_nsum) + 1, KM);

    // 6) codebook EMA update
    cbnew_kernel<<<(KS * GD) / 256, 256>>>(avg_syn, (const float*)p_esum_syn,
                                           (const float*)p_cl_syn, (const float*)p_nsum,
                                           out + OFF_CB_SYN, KS);
    cbnew_kernel<<<(KM * GD) / 256, 256>>>(avg_sem, (const float*)p_esum_sem,
                                           (const float*)p_cl_sem, ((const float*)p_nsum) + 1,
                                           out + OFF_CB_SEM, KM);

    // 7) zq gather + loss + idx output
    gather_loss_kernel<<<GN, 256>>>(zre_f, zim_f, (const int*)p_idx_syn, cb_syn,
                                    out + OFF_ZQ_SYN, out + OFF_IDX_SYN, (float*)p_loss);
    gather_loss_kernel<<<GN, 256>>>(zre_s, zim_s, (const int*)p_idx_sem, cb_sem,
                                    out + OFF_ZQ_SEM, out + OFF_IDX_SEM, (float*)p_loss);

    // 8) loss finalize
    finalize_loss_kernel<<<1, 1>>>((const float*)p_loss, out + OFF_LOSS);

    // 9) adjacency transform
    {
        size_t tot = (size_t)KS * KS;
        adj_kernel<<<(unsigned)((tot + 255) / 256), 256>>>(adj_syn, (const int*)p_pair_syn,
                                                           out + OFF_ADJ_SYN, tot);
    }
    {
        size_t tot = (size_t)KM * KM;
        adj_kernel<<<(unsigned)((tot + 255) / 256), 256>>>(adj_sem, (const int*)p_pair_sem,
                                                           out + OFF_ADJ_SEM, tot);
    }
    (void)in_sizes; (void)n_in; (void)out_size;
}

// round 4
// speedup vs baseline: 4.4045x; 3.7166x over previous
#include <cuda_runtime.h>
#include <cuda_bf16.h>
#include <math.h>
#include <float.h>
#include <stdint.h>

// Problem constants
#define GN   32768
#define GLD  256
#define GD   512
#define KS   1024
#define KM   4096
#define NUNITS 1280   // 256 syn units + 1024 sem units (each: 128 rows x 1024 codes)

// ---------------- scratch (static __device__, no allocation) ----------------
static __device__ float g_esum_syn[KS * GD];
static __device__ float g_esum_sem[KM * GD];
static __device__ float g_counts_syn[KS];
static __device__ float g_counts_sem[KM];
static __device__ int   g_pair_syn[(size_t)KS * KS];
static __device__ int   g_pair_sem[(size_t)KM * KM];
static __device__ int   g_idx_syn[GN];
static __device__ int   g_idx_sem[GN];
static __device__ float g_cnorm_syn[KS];
static __device__ float g_cnorm_sem[KM];
static __device__ float g_clnew_syn[KS];
static __device__ float g_clnew_sem[KM];
static __device__ float g_nsum[2];
static __device__ float g_loss[1];
static __device__ int   g_maxcn[2];   // float-as-int max of squared code norms
// bf16 copies (16B-aligned for uint4 access)
static __device__ __align__(16) __nv_bfloat16 g_zbf_syn[(size_t)GN * GD];
static __device__ __align__(16) __nv_bfloat16 g_zbf_sem[(size_t)GN * GD];
static __device__ __align__(16) __nv_bfloat16 g_cbf_syn[(size_t)KS * GD];
static __device__ __align__(16) __nv_bfloat16 g_cbf_sem[(size_t)KM * GD];
// candidates: per (unit, local row): 32 slots
static __device__ float g_cv[(size_t)NUNITS * 128 * 32];
static __device__ int   g_ck[(size_t)NUNITS * 128 * 32];

// ---------------- PTX helpers (arch-agnostic: ldmatrix + mma.sync) ----------
__device__ __forceinline__ uint32_t smem_u32(const void* p) {
    uint32_t a;
    asm("{ .reg .u64 t; cvta.to.shared.u64 t, %1; cvt.u32.u64 %0, t; }" : "=r"(a) : "l"(p));
    return a;
}
__device__ __forceinline__ void ldsm4(uint32_t& r0, uint32_t& r1, uint32_t& r2, uint32_t& r3,
                                      uint32_t addr) {
    asm volatile("ldmatrix.sync.aligned.m8n8.x4.shared.b16 {%0,%1,%2,%3}, [%4];"
                 : "=r"(r0), "=r"(r1), "=r"(r2), "=r"(r3) : "r"(addr));
}
__device__ __forceinline__ void mma_bf16(float* d, const uint32_t* a, uint32_t b0, uint32_t b1) {
    asm volatile("mma.sync.aligned.m16n8k16.row.col.f32.bf16.bf16.f32 "
                 "{%0,%1,%2,%3}, {%4,%5,%6,%7}, {%8,%9}, {%0,%1,%2,%3};"
                 : "+f"(d[0]), "+f"(d[1]), "+f"(d[2]), "+f"(d[3])
                 : "r"(a[0]), "r"(a[1]), "r"(a[2]), "r"(a[3]), "r"(b0), "r"(b1));
}

// ---------------- generic helpers ----------------
__device__ __forceinline__ float blk_reduce_256(float v) {
    __shared__ float sh[8];
    int lane = threadIdx.x & 31, w = threadIdx.x >> 5;
#pragma unroll
    for (int o = 16; o; o >>= 1) v += __shfl_down_sync(0xffffffffu, v, o);
    if (lane == 0) sh[w] = v;
    __syncthreads();
    if (w == 0) {
        v = (lane < 8) ? sh[lane] : 0.f;
#pragma unroll
        for (int o = 4; o; o >>= 1) v += __shfl_down_sync(0xffffffffu, v, o);
    }
    return v;
}

// ---------------- conversions ----------------
__global__ void cvt_z_kernel(const float* __restrict__ re, const float* __restrict__ im,
                             __nv_bfloat16* __restrict__ out) {
    size_t e = ((size_t)blockIdx.x * 256 + threadIdx.x) * 4;
    int n = (int)(e >> 9), d = (int)(e & 511);
    const float* s = (d < GLD) ? re + (size_t)n * GLD + d : im + (size_t)n * GLD + (d - GLD);
    float4 v = *(const float4*)s;
    __nv_bfloat162 a = __floats2bfloat162_rn(v.x, v.y);
    __nv_bfloat162 b = __floats2bfloat162_rn(v.z, v.w);
    ((__nv_bfloat162*)(out + e))[0] = a;
    ((__nv_bfloat162*)(out + e))[1] = b;
}
__global__ void cvt_cb_kernel(const float* __restrict__ cb, __nv_bfloat16* __restrict__ out) {
    size_t e = ((size_t)blockIdx.x * 256 + threadIdx.x) * 4;
    float4 v = *(const float4*)(cb + e);
    __nv_bfloat162 a = __floats2bfloat162_rn(v.x, v.y);
    __nv_bfloat162 b = __floats2bfloat162_rn(v.z, v.w);
    ((__nv_bfloat162*)(out + e))[0] = a;
    ((__nv_bfloat162*)(out + e))[1] = b;
}

// ---------------- code row norms (+ max reduce) ----------------
__global__ void rownorm_kernel(const float* __restrict__ cb, float* __restrict__ out,
                               int* __restrict__ mx) {
    int k = blockIdx.x;
    const float* row = cb + (size_t)k * GD;
    float s = 0.f;
    for (int d = threadIdx.x; d < GD; d += 256) {
        float v = row[d];
        s = fmaf(v, v, s);
    }
    s = blk_reduce_256(s);
    if (threadIdx.x == 0) {
        out[k] = s;
        atomicMax(mx, __float_as_int(s));
    }
}

// ---------------- HMMA bf16 distance pass ----------------
// Per unit (CTA, 256 thr = 8 warps in 2m x 4n): 128 rows x 1024 codes, D=512.
// Z resident in SMEM (128 x 512 bf16, row stride 1040B = 16B skew).
// Codebook streamed in 128 x 64 chunks (row stride 144B).
// Output: per row, 32 candidate (bf16-dist, k) slots (per-thread top2).
#define SM_CN   0
#define SM_Z    512
#define SM_C    (512 + 128 * 1040)                 // 133632
#define SM_SV   SM_C
#define SM_SK   (SM_C + 16384)
#define SM_TOTAL (SM_C + 32768)                    // 166400

__global__ __launch_bounds__(256, 1) void dist_hmma_kernel(
    const __nv_bfloat16* __restrict__ zbfA, const __nv_bfloat16* __restrict__ cbfA,
    const float* __restrict__ cnA,
    const __nv_bfloat16* __restrict__ zbfB, const __nv_bfloat16* __restrict__ cbfB,
    const float* __restrict__ cnB,
    float* __restrict__ cvout, int* __restrict__ ckout)
{
    extern __shared__ __align__(16) char smem[];
    float* sCN = (float*)(smem + SM_CN);
    char*  sZ  = smem + SM_Z;
    char*  sC  = smem + SM_C;
    float* sv  = (float*)(smem + SM_SV);
    int*   sk  = (int*)(smem + SM_SK);

    const int tid = threadIdx.x, wid = tid >> 5, lane = tid & 31;
    const int u = blockIdx.x;

    const __nv_bfloat16 *zsrc, *csrc;
    const float* cn;
    int rowBase, kBase;
    if (u < 256) {
        zsrc = zbfA; csrc = cbfA; cn = cnA; rowBase = u * 128; kBase = 0;
    } else {
        int v = u - 256;
        zsrc = zbfB; csrc = cbfB; cn = cnB;
        rowBase = (v >> 2) * 128; kBase = (v & 3) * 1024;
    }

    // load Z tile: 128 rows x 512 bf16
#pragma unroll
    for (int i = 0; i < 32; i++) {
        int c = tid + 256 * i;       // 16B chunk id, 0..8191
        int r = c >> 6, c8 = c & 63;
        uint4 v = *(const uint4*)(zsrc + (((size_t)(rowBase + r)) << 9) + c8 * 8);
        *(uint4*)(sZ + r * 1040 + c8 * 16) = v;
    }

    const int wm = wid >> 2, wn = wid & 3;
    const uint32_t zaddr0 = smem_u32(sZ) + (uint32_t)((wm * 64 + (lane & 15)) * 1040 + (lane >> 4) * 16);
    const uint32_t caddr0 = smem_u32(sC) +
        (uint32_t)((wn * 32 + ((lane >> 4) << 3) + (lane & 7)) * 144 + ((lane >> 3) & 1) * 16);

    float tv[8][2]; int tk[8][2];
#pragma unroll
    for (int i = 0; i < 8; i++)
#pragma unroll
        for (int s = 0; s < 2; s++) { tv[i][s] = FLT_MAX; tk[i][s] = 0; }

    for (int t = 0; t < 8; t++) {
        const int kTile = kBase + t * 128;
        float acc[4][4][4];
#pragma unroll
        for (int mt = 0; mt < 4; mt++)
#pragma unroll
            for (int nt = 0; nt < 4; nt++)
#pragma unroll
                for (int q = 0; q < 4; q++) acc[mt][nt][q] = 0.f;

        uint4 pf[4];
#pragma unroll
        for (int j = 0; j < 4; j++) {
            int c = tid + 256 * j, r = c >> 3, c8 = c & 7;
            pf[j] = *(const uint4*)(csrc + (((size_t)(kTile + r)) << 9) + c8 * 8);
        }
        for (int dc = 0; dc < 8; dc++) {
            __syncthreads();
            if (dc == 0 && tid < 128) sCN[tid] = cn[kTile + tid];
#pragma unroll
            for (int j = 0; j < 4; j++) {
                int c = tid + 256 * j, r = c >> 3, c8 = c & 7;
                *(uint4*)(sC + r * 144 + c8 * 16) = pf[j];
            }
            if (dc < 7) {
#pragma unroll
                for (int j = 0; j < 4; j++) {
                    int c = tid + 256 * j, r = c >> 3, c8 = c & 7;
                    pf[j] = *(const uint4*)(csrc + (((size_t)(kTile + r)) << 9) + (dc + 1) * 64 + c8 * 8);
                }
            }
            __syncthreads();
#pragma unroll
            for (int ks = 0; ks < 4; ks++) {
                uint32_t b[8];
                ldsm4(b[0], b[1], b[2], b[3], caddr0 + ks * 32);
                ldsm4(b[4], b[5], b[6], b[7], caddr0 + 16 * 144 + ks * 32);
                uint32_t a[4][4];
#pragma unroll
                for (int mt = 0; mt < 4; mt++)
                    ldsm4(a[mt][0], a[mt][1], a[mt][2], a[mt][3],
                          zaddr0 + (uint32_t)(mt * 16 * 1040 + (dc * 64 + ks * 16) * 2));
#pragma unroll
                for (int mt = 0; mt < 4; mt++)
#pragma unroll
                    for (int nt = 0; nt < 4; nt++)
                        mma_bf16(acc[mt][nt], a[mt], b[(nt >> 1) * 4 + (nt & 1) * 2],
                                 b[(nt >> 1) * 4 + (nt & 1) * 2 + 1]);
            }
        }
        // epilogue: fold tile into per-thread top-2 per row
#pragma unroll
        for (int mt = 0; mt < 4; mt++)
#pragma unroll
            for (int half = 0; half < 2; half++) {
                int i = mt * 2 + half;
#pragma unroll
                for (int nt = 0; nt < 4; nt++)
#pragma unroll
                    for (int c = 0; c < 2; c++) {
                        int col = wn * 32 + nt * 8 + (lane & 3) * 2 + c;
                        float s = acc[mt][nt][half * 2 + c];
                        float v = fmaf(-2.f, s, sCN[col]);
                        int k = kTile + col;
                        if (v < tv[i][0]) {
                            tv[i][1] = tv[i][0]; tk[i][1] = tk[i][0];
                            tv[i][0] = v; tk[i][0] = k;
                        } else if (v < tv[i][1]) {
                            tv[i][1] = v; tk[i][1] = k;
                        }
                    }
            }
    }

    // stage candidates in SMEM (overwrites sC region), then coalesced store
    __syncthreads();
#pragma unroll
    for (int i = 0; i < 8; i++) {
        int r = wm * 64 + (i >> 1) * 16 + (i & 1) * 8 + (lane >> 2);
        int slot0 = wn * 8 + (lane & 3) * 2;
#pragma unroll
        for (int s = 0; s < 2; s++) {
            sv[r * 32 + slot0 + s] = tv[i][s];
            sk[r * 32 + slot0 + s] = tk[i][s];
        }
    }
    __syncthreads();
#pragma unroll
    for (int j = 0; j < 16; j++) {
        int idx = tid + 256 * j;
        cvout[(size_t)u * 4096 + idx] = sv[idx];
        ckout[(size_t)u * 4096 + idx] = sk[idx];
    }
}

// ---------------- exact fp32 refinement ----------------
__global__ __launch_bounds__(256) void refine_kernel(
    const float* __restrict__ zreA, const float* __restrict__ zimA,
    const float* __restrict__ cbA, const float* __restrict__ cnA,
    const float* __restrict__ zreB, const float* __restrict__ zimB,
    const float* __restrict__ cbB, const float* __restrict__ cnB,
    const float* __restrict__ cv, const int* __restrict__ ck,
    const int* __restrict__ maxcn,
    int* __restrict__ idxA, int* __restrict__ idxB)
{
    int wid = threadIdx.x >> 5, lane = threadIdx.x & 31;
    int gw = blockIdx.x * 8 + wid;
    int n = gw >> 1, cbk = gw & 1;
    const float *zre, *zim, *cb, *cn;
    int* idxo;
    int cnt;
    size_t base;
    if (cbk == 0) {
        zre = zreA; zim = zimA; cb = cbA; cn = cnA; idxo = idxA;
        cnt = 32; base = ((size_t)(n >> 7) * 128 + (n & 127)) * 32;
    } else {
        zre = zreB; zim = zimB; cb = cbB; cn = cnB; idxo = idxB;
        cnt = 128; base = ((size_t)(256 + (n >> 7) * 4) * 128 + (n & 127)) * 32;
    }

    float zr[16];
    float zn2 = 0.f;
#pragma unroll
    for (int j = 0; j < 16; j++) {
        int d = lane + 32 * j;
        float z = (d < GLD) ? zre[(size_t)n * GLD + d] : zim[(size_t)n * GLD + d - GLD];
        zr[j] = z;
        zn2 = fmaf(z, z, zn2);
    }
#pragma unroll
    for (int o = 16; o; o >>= 1) zn2 += __shfl_xor_sync(0xffffffffu, zn2, o);

    // min over candidate bf16 distances (lane-strided)
    float vb = FLT_MAX;
    for (int c = lane; c < cnt; c += 32) {
        float v = cv[base + (size_t)(c >> 5) * 4096 + (c & 31)];
        vb = fminf(vb, v);
    }
#pragma unroll
    for (int o = 16; o; o >>= 1) vb = fminf(vb, __shfl_xor_sync(0xffffffffu, vb, o));

    float maxc2 = __int_as_float(maxcn[cbk]);
    float vlim = vb + 0.03125f * sqrtf(zn2 * maxc2) + 0.125f;

    float bd = FLT_MAX; int bk = 0x7fffffff;
    for (int i = 0; i < cnt; i++) {
        size_t a = base + (size_t)(i >> 5) * 4096 + (i & 31);
        float v = cv[a];
        if (v <= vlim) {
            int k = ck[a];
            const float* crow = cb + (size_t)k * GD;
            float s = 0.f;
#pragma unroll
            for (int j = 0; j < 16; j++) s = fmaf(zr[j], crow[lane + 32 * j], s);
#pragma unroll
            for (int o = 16; o; o >>= 1) s += __shfl_xor_sync(0xffffffffu, s, o);
            float d = fmaf(-2.f, s, cn[k]);
            if (d < bd || (d == bd && k < bk)) { bd = d; bk = k; }
        }
    }
    if (lane == 0) idxo[n] = bk;
}

// ---------------- scatter: counts, pair counts, embed_sum ----------------
__global__ void scatter_kernel(
    const float* __restrict__ zre, const float* __restrict__ zim,
    const int* __restrict__ idx, const int* __restrict__ prev,
    float* __restrict__ counts, float* __restrict__ esum,
    int* __restrict__ pair, int K)
{
    int n = blockIdx.x;
    int i = idx[n];
    int t = threadIdx.x;
    if (t == 0) {
        atomicAdd(&counts[i], 1.f);
        atomicAdd(&pair[(size_t)prev[n] * K + i], 1);
    }
    const float* zr = zre + (size_t)n * GLD;
    const float* zi = zim + (size_t)n * GLD;
    float* es = esum + (size_t)i * GD;
    for (int d = t; d < GLD; d += 256) {
        atomicAdd(&es[d], zr[d]);
        atomicAdd(&es[d + GLD], zi[d]);
    }
}

// ---------------- cluster_size EMA + n reduction ----------------
__global__ void clnew_kernel(const float* __restrict__ cl, const float* __restrict__ counts,
                             float* __restrict__ clnew, float* __restrict__ nsum, int K)
{
    int k = blockIdx.x * 256 + threadIdx.x;
    float v = 0.f;
    if (k < K) {
        v = cl[k] * 0.99f + 0.01f * counts[k];
        clnew[k] = v;
    }
    v = blk_reduce_256(v);
    if (threadIdx.x == 0) atomicAdd(nsum, v);
}

// ---------------- codebook EMA update ----------------
__global__ void cbnew_kernel(const float* __restrict__ avg, const float* __restrict__ esum,
                             const float* __restrict__ clnew, const float* __restrict__ nsum,
                             float* __restrict__ out, int K)
{
    size_t idx = (size_t)blockIdx.x * 256 + threadIdx.x;
    int k = (int)(idx >> 9);
    float n = *nsum;
    float cs = (clnew[k] + 1e-6f) / (n + (float)K * 1e-6f) * n;
    float a = avg[idx] * 0.99f + 0.01f * esum[idx];
    out[idx] = a / cs;
}

// ---------------- zq gather + loss accumulation + idx-as-float ----------------
__global__ void gather_loss_kernel(
    const float* __restrict__ zre, const float* __restrict__ zim,
    const int* __restrict__ idx, const float* __restrict__ cb,
    float* __restrict__ zq, float* __restrict__ idxf, float* __restrict__ lacc)
{
    int n = blockIdx.x;
    int i = idx[n];
    int t = threadIdx.x;
    if (t == 0) idxf[n] = (float)i;
    const float* crow = cb + (size_t)i * GD;
    float s = 0.f;
    for (int d = t; d < GD; d += 256) {
        float q = crow[d];
        float z = (d < GLD) ? zre[(size_t)n * GLD + d]
                            : zim[(size_t)n * GLD + d - GLD];
        zq[(size_t)n * GD + d] = q;
        float df = q - z;
        s = fmaf(df, df, s);
    }
    s = blk_reduce_256(s);
    if (t == 0) atomicAdd(lacc, s);
}

__global__ void finalize_loss_kernel(const float* __restrict__ lacc, float* __restrict__ out) {
    out[0] = 1.25f * lacc[0] / 16777216.f;
}

// ---------------- adjacency transform ----------------
__global__ void adj_kernel(const float* __restrict__ adj, const int* __restrict__ cnt,
                           float* __restrict__ out, size_t total)
{
    size_t i = (size_t)blockIdx.x * 256 + threadIdx.x;
    if (i >= total) return;
    int c = cnt[i];
    float a = adj[i];
    if (c == 0) { out[i] = a; return; }
    float p = powf(0.99f, (float)c);
    out[i] = a * p + (1.f - p) / 0.01f;
}

// ---------------- launch ----------------
extern "C" void kernel_launch(void* const* d_in, const int* in_sizes, int n_in,
                              void* d_out, int out_size)
{
    const float* zre_f = (const float*)d_in[0];
    const float* zim_f = (const float*)d_in[1];
    const float* zre_s = (const float*)d_in[2];
    const float* zim_s = (const float*)d_in[3];
    const int*   prev_syn = (const int*)d_in[4];
    const int*   prev_sem = (const int*)d_in[5];
    const float* cb_syn = (const float*)d_in[6];
    const float* cb_sem = (const float*)d_in[7];
    const float* cl_syn = (const float*)d_in[8];
    const float* avg_syn = (const float*)d_in[9];
    const float* cl_sem = (const float*)d_in[10];
    const float* avg_sem = (const float*)d_in[11];
    const float* adj_syn = (const float*)d_in[12];
    const float* adj_sem = (const float*)d_in[13];

    float* out = (float*)d_out;
    const size_t OFF_ZQ_SYN = 0;
    const size_t OFF_ZQ_SEM = OFF_ZQ_SYN + (size_t)GN * GD;
    const size_t OFF_LOSS   = OFF_ZQ_SEM + (size_t)GN * GD;
    const size_t OFF_IDX_SYN = OFF_LOSS + 1;
    const size_t OFF_IDX_SEM = OFF_IDX_SYN + GN;
    const size_t OFF_CB_SYN  = OFF_IDX_SEM + GN;
    const size_t OFF_CB_SEM  = OFF_CB_SYN + (size_t)KS * GD;
    const size_t OFF_ADJ_SYN = OFF_CB_SEM + (size_t)KM * GD;
    const size_t OFF_ADJ_SEM = OFF_ADJ_SYN + (size_t)KS * KS;

    void *p_esum_syn, *p_esum_sem, *p_cnt_syn, *p_cnt_sem, *p_pair_syn, *p_pair_sem;
    void *p_idx_syn, *p_idx_sem, *p_cn_syn, *p_cn_sem, *p_cl_syn, *p_cl_sem, *p_nsum, *p_loss;
    void *p_maxcn, *p_zbf_syn, *p_zbf_sem, *p_cbf_syn, *p_cbf_sem, *p_cv, *p_ck;
    cudaGetSymbolAddress(&p_esum_syn, g_esum_syn);
    cudaGetSymbolAddress(&p_esum_sem, g_esum_sem);
    cudaGetSymbolAddress(&p_cnt_syn, g_counts_syn);
    cudaGetSymbolAddress(&p_cnt_sem, g_counts_sem);
    cudaGetSymbolAddress(&p_pair_syn, g_pair_syn);
    cudaGetSymbolAddress(&p_pair_sem, g_pair_sem);
    cudaGetSymbolAddress(&p_idx_syn, g_idx_syn);
    cudaGetSymbolAddress(&p_idx_sem, g_idx_sem);
    cudaGetSymbolAddress(&p_cn_syn, g_cnorm_syn);
    cudaGetSymbolAddress(&p_cn_sem, g_cnorm_sem);
    cudaGetSymbolAddress(&p_cl_syn, g_clnew_syn);
    cudaGetSymbolAddress(&p_cl_sem, g_clnew_sem);
    cudaGetSymbolAddress(&p_nsum, g_nsum);
    cudaGetSymbolAddress(&p_loss, g_loss);
    cudaGetSymbolAddress(&p_maxcn, g_maxcn);
    cudaGetSymbolAddress(&p_zbf_syn, g_zbf_syn);
    cudaGetSymbolAddress(&p_zbf_sem, g_zbf_sem);
    cudaGetSymbolAddress(&p_cbf_syn, g_cbf_syn);
    cudaGetSymbolAddress(&p_cbf_sem, g_cbf_sem);
    cudaGetSymbolAddress(&p_cv, g_cv);
    cudaGetSymbolAddress(&p_ck, g_ck);

    cudaFuncSetAttribute(dist_hmma_kernel,
                         cudaFuncAttributeMaxDynamicSharedMemorySize, SM_TOTAL);

    // 1) zero scratch
    cudaMemsetAsync(p_esum_syn, 0, (size_t)KS * GD * sizeof(float));
    cudaMemsetAsync(p_esum_sem, 0, (size_t)KM * GD * sizeof(float));
    cudaMemsetAsync(p_cnt_syn, 0, KS * sizeof(float));
    cudaMemsetAsync(p_cnt_sem, 0, KM * sizeof(float));
    cudaMemsetAsync(p_pair_syn, 0, (size_t)KS * KS * sizeof(int));
    cudaMemsetAsync(p_pair_sem, 0, (size_t)KM * KM * sizeof(int));
    cudaMemsetAsync(p_nsum, 0, 2 * sizeof(float));
    cudaMemsetAsync(p_loss, 0, sizeof(float));
    cudaMemsetAsync(p_maxcn, 0, 2 * sizeof(int));

    // 2) conversions
    cvt_z_kernel<<<(GN * GD) / 1024, 256>>>(zre_f, zim_f, (__nv_bfloat16*)p_zbf_syn);
    cvt_z_kernel<<<(GN * GD) / 1024, 256>>>(zre_s, zim_s, (__nv_bfloat16*)p_zbf_sem);
    cvt_cb_kernel<<<(KS * GD) / 1024, 256>>>(cb_syn, (__nv_bfloat16*)p_cbf_syn);
    cvt_cb_kernel<<<(KM * GD) / 1024, 256>>>(cb_sem, (__nv_bfloat16*)p_cbf_sem);

    // 3) code norms + max
    rownorm_kernel<<<KS, 256>>>(cb_syn, (float*)p_cn_syn, (int*)p_maxcn);
    rownorm_kernel<<<KM, 256>>>(cb_sem, (float*)p_cn_sem, ((int*)p_maxcn) + 1);

    // 4) HMMA approximate distance pass
    dist_hmma_kernel<<<NUNITS, 256, SM_TOTAL>>>(
        (const __nv_bfloat16*)p_zbf_syn, (const __nv_bfloat16*)p_cbf_syn, (const float*)p_cn_syn,
        (const __nv_bfloat16*)p_zbf_sem, (const __nv_bfloat16*)p_cbf_sem, (const float*)p_cn_sem,
        (float*)p_cv, (int*)p_ck);

    // 5) exact fp32 refinement -> final indices
    refine_kernel<<<(2 * GN) / 8, 256>>>(
        zre_f, zim_f, cb_syn, (const float*)p_cn_syn,
        zre_s, zim_s, cb_sem, (const float*)p_cn_sem,
        (const float*)p_cv, (const int*)p_ck, (const int*)p_maxcn,
        (int*)p_idx_syn, (int*)p_idx_sem);

    // 6) scatter reductions
    scatter_kernel<<<GN, 256>>>(zre_f, zim_f, (const int*)p_idx_syn, prev_syn,
                                (float*)p_cnt_syn, (float*)p_esum_syn,
                                (int*)p_pair_syn, KS);
    scatter_kernel<<<GN, 256>>>(zre_s, zim_s, (const int*)p_idx_sem, prev_sem,
                                (float*)p_cnt_sem, (float*)p_esum_sem,
                                (int*)p_pair_sem, KM);

    // 7) cluster size EMA + n
    clnew_kernel<<<KS / 256, 256>>>(cl_syn, (const float*)p_cnt_syn,
                                    (float*)p_cl_syn, (float*)p_nsum, KS);
    clnew_kernel<<<KM / 256, 256>>>(cl_sem, (const float*)p_cnt_sem,
                                    (float*)p_cl_sem, ((float*)p_nsum) + 1, KM);

    // 8) codebook EMA update
    cbnew_kernel<<<(KS * GD) / 256, 256>>>(avg_syn, (const float*)p_esum_syn,
                                           (const float*)p_cl_syn, (const float*)p_nsum,
                                           out + OFF_CB_SYN, KS);
    cbnew_kernel<<<(KM * GD) / 256, 256>>>(avg_sem, (const float*)p_esum_sem,
                                           (const float*)p_cl_sem, ((const float*)p_nsum) + 1,
                                           out + OFF_CB_SEM, KM);

    // 9) zq gather + loss + idx output
    gather_loss_kernel<<<GN, 256>>>(zre_f, zim_f, (const int*)p_idx_syn, cb_syn,
                                    out + OFF_ZQ_SYN, out + OFF_IDX_SYN, (float*)p_loss);
    gather_loss_kernel<<<GN, 256>>>(zre_s, zim_s, (const int*)p_idx_sem, cb_sem,
                                    out + OFF_ZQ_SEM, out + OFF_IDX_SEM, (float*)p_loss);

    // 10) loss finalize
    finalize_loss_kernel<<<1, 1>>>((const float*)p_loss, out + OFF_LOSS);

    // 11) adjacency transform
    {
        size_t tot = (size_t)KS * KS;
        adj_kernel<<<(unsigned)((tot + 255) / 256), 256>>>(adj_syn, (const int*)p_pair_syn,
                                                           out + OFF_ADJ_SYN, tot);
    }
    {
        size_t tot = (size_t)KM * KM;
        adj_kernel<<<(unsigned)((tot + 255) / 256), 256>>>(adj_sem, (const int*)p_pair_sem,
                                                           out + OFF_ADJ_SEM, tot);
    }
    (void)in_sizes; (void)n_in; (void)out_size;
}